// round 9
// baseline (speedup 1.0000x reference)
#include <cuda_runtime.h>
#include <cuda_fp16.h>
#include <cstdint>

#define NEXP 8
#define NTOK 8192
#define H    2048
#define I2   4096
#define ID   2048
#define MAXTILES 136
#define PADSLOTS (MAXTILES*128)
#define SMEM_BYTES 98304   /* 3 stages x 32KB */

// ---------------- static scratch ----------------
__device__ int    g_count[NEXP];
__device__ int    g_offset[NEXP];
__device__ int    g_ntiles;
__device__ int    g_tile_e[MAXTILES];
__device__ int    g_tok[NEXP*NTOK];
__device__ int    g_slot[NTOK*2];
__device__ float2 g_wv[NTOK];
__device__ __align__(16) __half g_xh [(size_t)PADSLOTS*H];
__device__ __align__(16) __half g_yh [(size_t)PADSLOTS*ID];
__device__ __align__(16) float  g_ob [(size_t)PADSLOTS*H];
__device__ __align__(16) __half g_w1h[(size_t)NEXP*I2*H];
__device__ __align__(16) __half g_w2h[(size_t)NEXP*H*ID];

// ---------------- helpers ----------------
__device__ __forceinline__ uint32_t smem_u32(const void* p){
    uint32_t a;
    asm("{ .reg .u64 t; cvta.to.shared.u64 t, %1; cvt.u32.u64 %0, t; }" : "=r"(a) : "l"(p));
    return a;
}
#define CPA(dst,src) asm volatile("cp.async.cg.shared.global [%0], [%1], 16;" :: "r"(dst), "l"(src))
#define CPC()  asm volatile("cp.async.commit_group;" ::: "memory")
#define CPW(n) asm volatile("cp.async.wait_group %0;" :: "n"(n) : "memory")
#define LDSM4(r0,r1,r2,r3,addr) \
    asm volatile("ldmatrix.sync.aligned.m8n8.x4.shared.b16 {%0,%1,%2,%3}, [%4];" \
        : "=r"(r0),"=r"(r1),"=r"(r2),"=r"(r3) : "r"(addr))
#define MMA(c,a,b) \
    asm volatile("mma.sync.aligned.m16n8k16.row.col.f32.f16.f16.f32 " \
        "{%0,%1,%2,%3},{%4,%5,%6,%7},{%8,%9},{%0,%1,%2,%3};" \
        : "+f"((c)[0]),"+f"((c)[1]),"+f"((c)[2]),"+f"((c)[3]) \
        : "r"((a)[0]),"r"((a)[1]),"r"((a)[2]),"r"((a)[3]),"r"((b)[0]),"r"((b)[1]))

// ---------------- small kernels ----------------
__global__ void k_init(){ if (threadIdx.x < NEXP) g_count[threadIdx.x] = 0; }

__global__ void k_gate(const float* __restrict__ x, const float* __restrict__ gw,
                       const float* __restrict__ gb){
    int warp = (blockIdx.x * blockDim.x + threadIdx.x) >> 5;
    int lane = threadIdx.x & 31;
    if (warp >= NTOK) return;
    const float* xr = x + (size_t)warp * H;
    float acc[NEXP];
#pragma unroll
    for (int e = 0; e < NEXP; e++) acc[e] = 0.f;
    for (int i = lane; i < H; i += 32){
        float xv = xr[i];
#pragma unroll
        for (int e = 0; e < NEXP; e++) acc[e] += xv * gw[e*H + i];
    }
#pragma unroll
    for (int e = 0; e < NEXP; e++)
#pragma unroll
        for (int o = 16; o > 0; o >>= 1) acc[e] += __shfl_xor_sync(0xffffffffu, acc[e], o);
    if (lane == 0){
        float lg[NEXP];
#pragma unroll
        for (int e = 0; e < NEXP; e++) lg[e] = acc[e] + gb[e];
        int b0 = 0;
#pragma unroll
        for (int e = 1; e < NEXP; e++) if (lg[e] > lg[b0]) b0 = e;
        int b1 = -1;
#pragma unroll
        for (int e = 0; e < NEXP; e++){ if (e == b0) continue; if (b1 < 0 || lg[e] > lg[b1]) b1 = e; }
        float e1 = expf(lg[b1] - lg[b0]);
        float inv = 1.f / (1.f + e1);
        g_wv[warp] = make_float2(inv, e1 * inv);
        int p0 = atomicAdd(&g_count[b0], 1); g_tok[b0*NTOK + p0] = warp*2 + 0;
        int p1 = atomicAdd(&g_count[b1], 1); g_tok[b1*NTOK + p1] = warp*2 + 1;
    }
}

__global__ void k_scan(){
    if (threadIdx.x == 0){
        int base = 0, nt = 0;
        for (int e = 0; e < NEXP; e++){
            g_offset[e] = base;
            int t = (g_count[e] + 127) >> 7;
            for (int i = 0; i < t; i++) g_tile_e[nt++] = e;
            base += t * 128;
        }
        g_ntiles = nt;
    }
}

// gather x rows -> fp16 compacted
__global__ void k_gather(const float* __restrict__ x){
    int e = blockIdx.x, pos0 = blockIdx.y * 8, cnt = g_count[e];
    if (pos0 >= cnt) return;
    int off = g_offset[e];
    for (int r = 0; r < 8; r++){
        int pos = pos0 + r; if (pos >= cnt) break;
        int code = g_tok[e*NTOK + pos], t = code >> 1, slot = off + pos;
        if (threadIdx.x == 0) g_slot[code] = slot;
        const float4* src = (const float4*)(x + (size_t)t * H);
        uint4* dst = (uint4*)(g_xh + (size_t)slot * H);
        for (int i = threadIdx.x; i < H/8; i += blockDim.x){
            float4 v0 = src[2*i], v1 = src[2*i+1];
            __half2 h0 = __floats2half2_rn(v0.x, v0.y), h1 = __floats2half2_rn(v0.z, v0.w);
            __half2 h2 = __floats2half2_rn(v1.x, v1.y), h3 = __floats2half2_rn(v1.z, v1.w);
            uint4 u;
            u.x = *(uint32_t*)&h0; u.y = *(uint32_t*)&h1;
            u.z = *(uint32_t*)&h2; u.w = *(uint32_t*)&h3;
            dst[i] = u;
        }
    }
}

// fp32 weights -> fp16
__global__ void k_cvt(const float4* __restrict__ W, uint4* __restrict__ O){
    size_t i = (size_t)blockIdx.x * blockDim.x + threadIdx.x;
    float4 v0 = W[2*i], v1 = W[2*i+1];
    __half2 h0 = __floats2half2_rn(v0.x, v0.y), h1 = __floats2half2_rn(v0.z, v0.w);
    __half2 h2 = __floats2half2_rn(v1.x, v1.y), h3 = __floats2half2_rn(v1.z, v1.w);
    uint4 u;
    u.x = *(uint32_t*)&h0; u.y = *(uint32_t*)&h1;
    u.z = *(uint32_t*)&h2; u.w = *(uint32_t*)&h3;
    O[i] = u;
}

// ---------------- fp16 mma.sync GEMM: C(128x128) = A(128xK) * W(128xK)^T ----------------
template<bool SWIGLU>
__global__ __launch_bounds__(256, 2) void k_hmma(const __half* __restrict__ Wh,
                                                 const float* __restrict__ Bb){
    int tile = blockIdx.y;
    if (tile >= g_ntiles) return;
    const int Nr = SWIGLU ? I2 : H;
    int e = g_tile_e[tile], n0 = blockIdx.x * 128;
    extern __shared__ __align__(16) char smem[];
    uint32_t sb = smem_u32(smem);
    int tid = threadIdx.x, lane = tid & 31, wid = tid >> 5;
    int wm = wid >> 2, wn = wid & 3;
    const __half* Ag = (SWIGLU ? g_xh : g_yh) + (size_t)tile * 128 * H;
    const __half* Bg = Wh + ((size_t)e * Nr + n0) * H;

    float acc[4][4][4];
#pragma unroll
    for (int mt = 0; mt < 4; mt++)
#pragma unroll
        for (int j = 0; j < 4; j++)
#pragma unroll
            for (int q = 0; q < 4; q++) acc[mt][j][q] = 0.f;

#define ISSUE(st, kt) do{ \
        uint32_t base = sb + (uint32_t)(st)*32768u; \
        int k0 = (kt)*64; \
        _Pragma("unroll") \
        for (int i = 0; i < 4; i++){ \
            int c = tid + i*256, row = c >> 3, ch = c & 7; \
            uint32_t d = base + (uint32_t)(row*128 + ((ch ^ (row & 7))*16)); \
            CPA(d,          Ag + (size_t)row*H + k0 + ch*8); \
            CPA(d + 16384u, Bg + (size_t)row*H + k0 + ch*8); \
        } \
        CPC(); \
    }while(0)

    ISSUE(0, 0);
    ISSUE(1, 1);
    for (int it = 0; it < 32; it++){
        if (it == 31) CPW(0); else CPW(1);
        __syncthreads();
        if (it + 2 < 32) ISSUE((it + 2) % 3, it + 2);
        uint32_t sA = sb + (uint32_t)(it % 3)*32768u, sB = sA + 16384u;
#pragma unroll
        for (int ks = 0; ks < 4; ks++){
            uint32_t af[4][4], bf[4][2];
#pragma unroll
            for (int mt = 0; mt < 4; mt++){
                int row = wm*64 + mt*16 + ((lane >> 3) & 1)*8 + (lane & 7);
                int ch  = ks*2 + (lane >> 4);
                uint32_t a = sA + (uint32_t)(row*128 + ((ch ^ (row & 7))*16));
                LDSM4(af[mt][0], af[mt][1], af[mt][2], af[mt][3], a);
            }
#pragma unroll
            for (int nb = 0; nb < 2; nb++){
                int row = wn*32 + nb*16 + (lane >> 4)*8 + (lane & 7);
                int ch  = ks*2 + ((lane >> 3) & 1);
                uint32_t a = sB + (uint32_t)(row*128 + ((ch ^ (row & 7))*16));
                LDSM4(bf[2*nb][0], bf[2*nb][1], bf[2*nb+1][0], bf[2*nb+1][1], a);
            }
#pragma unroll
            for (int mt = 0; mt < 4; mt++)
#pragma unroll
                for (int j = 0; j < 4; j++) MMA(acc[mt][j], af[mt], bf[j]);
        }
    }
    __syncthreads();

    const float* bs = Bb + (size_t)e * Nr + n0;
    int g = lane >> 2, cp = lane & 3;
    if (SWIGLU){
        __half* ysm = (__half*)smem;   // [128][72]
#pragma unroll
        for (int mt = 0; mt < 4; mt++){
            int r0 = wm*64 + mt*16 + g;
#pragma unroll
            for (int j = 0; j < 4; j++){
                int colb = wn*32 + j*8 + 2*cp;
                float bg = bs[colb], bl = bs[colb + 1];
                int yc = colb >> 1;
                float g0 = acc[mt][j][0] + bg, l0 = acc[mt][j][1] + bl;
                float g1 = acc[mt][j][2] + bg, l1 = acc[mt][j][3] + bl;
                ysm[r0*72 + yc]     = __float2half_rn(g0 * (1.f/(1.f + expf(-1.702f*g0))) * (l0 + 1.f));
                ysm[(r0+8)*72 + yc] = __float2half_rn(g1 * (1.f/(1.f + expf(-1.702f*g1))) * (l1 + 1.f));
            }
        }
        __syncthreads();
#pragma unroll
        for (int i = 0; i < 4; i++){
            int id = tid + i*256;           // 1024 chunks of 8 halves
            int row = id >> 3, cc = (id & 7)*8;
            uint4 v = *(const uint4*)(ysm + row*72 + cc);
            *(uint4*)(g_yh + (size_t)(tile*128 + row)*ID + (n0 >> 1) + cc) = v;
        }
    } else {
        float* osm = (float*)smem;      // [128][132]
#pragma unroll
        for (int mt = 0; mt < 4; mt++){
            int r0 = wm*64 + mt*16 + g;
#pragma unroll
            for (int j = 0; j < 4; j++){
                int colb = wn*32 + j*8 + 2*cp;
                float bg = bs[colb], bl = bs[colb + 1];
                osm[r0*132 + colb]       = acc[mt][j][0] + bg;
                osm[r0*132 + colb + 1]   = acc[mt][j][1] + bl;
                osm[(r0+8)*132 + colb]   = acc[mt][j][2] + bg;
                osm[(r0+8)*132 + colb+1] = acc[mt][j][3] + bl;
            }
        }
        __syncthreads();
#pragma unroll
        for (int i = 0; i < 16; i++){
            int id = tid + i*256;           // 4096 float4
            int row = id >> 5, c4 = id & 31;
            float4 v = *(const float4*)(osm + row*132 + c4*4);
            *((float4*)(g_ob + (size_t)(tile*128 + row)*H + n0) + c4) = v;
        }
    }
#undef ISSUE
}

__global__ void k_comb(float* __restrict__ out){
    int gid = blockIdx.x * blockDim.x + threadIdx.x;
    if (gid >= NTOK * (H/4)) return;
    int t = gid / (H/4), c4 = gid % (H/4);
    int s0 = g_slot[2*t], s1 = g_slot[2*t + 1];
    float2 w = g_wv[t];
    float4 a = *((const float4*)(g_ob + (size_t)s0 * H) + c4);
    float4 b = *((const float4*)(g_ob + (size_t)s1 * H) + c4);
    float4 r;
    r.x = w.x*a.x + w.y*b.x; r.y = w.x*a.y + w.y*b.y;
    r.z = w.x*a.z + w.y*b.z; r.w = w.x*a.w + w.y*b.w;
    *((float4*)out + gid) = r;
}

// ---------------- launcher ----------------
extern "C" void kernel_launch(void* const* d_in, const int* in_sizes, int n_in,
                              void* d_out, int out_size){
    const float* x  = (const float*)d_in[0];
    const float* gw = (const float*)d_in[1];
    const float* gb = (const float*)d_in[2];
    const float* w1 = (const float*)d_in[3];
    const float* b1 = (const float*)d_in[4];
    const float* w2 = (const float*)d_in[5];
    const float* b2 = (const float*)d_in[6];
    float* out = (float*)d_out;

    cudaFuncSetAttribute(k_hmma<true >, cudaFuncAttributeMaxDynamicSharedMemorySize, SMEM_BYTES);
    cudaFuncSetAttribute(k_hmma<false>, cudaFuncAttributeMaxDynamicSharedMemorySize, SMEM_BYTES);

    k_init<<<1, 32>>>();
    k_gate<<<NTOK/8, 256>>>(x, gw, gb);
    k_scan<<<1, 32>>>();
    k_gather<<<dim3(NEXP, NTOK/8), 256>>>(x);
    k_cvt<<<32768, 256>>>((const float4*)w1, (uint4*)g_w1h);
    k_cvt<<<16384, 256>>>((const float4*)w2, (uint4*)g_w2h);
    k_hmma<true ><<<dim3(32, MAXTILES), 256, SMEM_BYTES>>>(g_w1h, b1);
    k_hmma<false><<<dim3(16, MAXTILES), 256, SMEM_BYTES>>>(g_w2h, b2);
    k_comb<<<(NTOK*(H/4) + 255)/256, 256>>>(out);
}

// round 11
// speedup vs baseline: 2.1204x; 2.1204x over previous
#include <cuda_runtime.h>
#include <cuda_fp16.h>
#include <cstdint>

#define NEXP 8
#define NTOK 8192
#define H    2048
#define I2   4096
#define ID   2048
#define MAXTILES 136
#define PADSLOTS (MAXTILES*128)

// ---------------- static scratch ----------------
__device__ int    g_count[NEXP];
__device__ int    g_offset[NEXP];
__device__ int    g_ntiles;
__device__ int    g_tile_e[MAXTILES];
__device__ int    g_tok[NEXP*NTOK];
__device__ int    g_slot[NTOK*2];
__device__ float2 g_wv[NTOK];
__device__ __align__(16) __half g_xh [(size_t)PADSLOTS*H];
__device__ __align__(16) __half g_yh [(size_t)PADSLOTS*ID];
__device__ __align__(16) float  g_ob [(size_t)PADSLOTS*H];
__device__ __align__(16) __half g_w1h[(size_t)NEXP*I2*H];
__device__ __align__(16) __half g_w2h[(size_t)NEXP*H*ID];

// ---------------- small kernels ----------------
__global__ void k_init(){ if (threadIdx.x < NEXP) g_count[threadIdx.x] = 0; }

__global__ void k_gate(const float* __restrict__ x, const float* __restrict__ gw,
                       const float* __restrict__ gb){
    int warp = (blockIdx.x * blockDim.x + threadIdx.x) >> 5;
    int lane = threadIdx.x & 31;
    if (warp >= NTOK) return;
    const float* xr = x + (size_t)warp * H;
    float acc[NEXP];
#pragma unroll
    for (int e = 0; e < NEXP; e++) acc[e] = 0.f;
    for (int i = lane; i < H; i += 32){
        float xv = xr[i];
#pragma unroll
        for (int e = 0; e < NEXP; e++) acc[e] += xv * gw[e*H + i];
    }
#pragma unroll
    for (int e = 0; e < NEXP; e++)
#pragma unroll
        for (int o = 16; o > 0; o >>= 1) acc[e] += __shfl_xor_sync(0xffffffffu, acc[e], o);
    if (lane == 0){
        float lg[NEXP];
#pragma unroll
        for (int e = 0; e < NEXP; e++) lg[e] = acc[e] + gb[e];
        int b0 = 0;
#pragma unroll
        for (int e = 1; e < NEXP; e++) if (lg[e] > lg[b0]) b0 = e;
        int b1 = -1;
#pragma unroll
        for (int e = 0; e < NEXP; e++){ if (e == b0) continue; if (b1 < 0 || lg[e] > lg[b1]) b1 = e; }
        float e1 = expf(lg[b1] - lg[b0]);
        float inv = 1.f / (1.f + e1);
        g_wv[warp] = make_float2(inv, e1 * inv);
        int p0 = atomicAdd(&g_count[b0], 1); g_tok[b0*NTOK + p0] = warp*2 + 0;
        int p1 = atomicAdd(&g_count[b1], 1); g_tok[b1*NTOK + p1] = warp*2 + 1;
    }
}

__global__ void k_scan(){
    if (threadIdx.x == 0){
        int base = 0, nt = 0;
        for (int e = 0; e < NEXP; e++){
            g_offset[e] = base;
            int t = (g_count[e] + 127) >> 7;
            for (int i = 0; i < t; i++) g_tile_e[nt++] = e;
            base += t * 128;
        }
        g_ntiles = nt;
    }
}

// gather x rows -> fp16 compacted
__global__ void k_gather(const float* __restrict__ x){
    int e = blockIdx.x, pos0 = blockIdx.y * 8, cnt = g_count[e];
    if (pos0 >= cnt) return;
    int off = g_offset[e];
    for (int r = 0; r < 8; r++){
        int pos = pos0 + r; if (pos >= cnt) break;
        int code = g_tok[e*NTOK + pos], t = code >> 1, slot = off + pos;
        if (threadIdx.x == 0) g_slot[code] = slot;
        const float4* src = (const float4*)(x + (size_t)t * H);
        uint4* dst = (uint4*)(g_xh + (size_t)slot * H);
        for (int i = threadIdx.x; i < H/8; i += blockDim.x){
            float4 v0 = src[2*i], v1 = src[2*i+1];
            __half2 h0 = __floats2half2_rn(v0.x, v0.y), h1 = __floats2half2_rn(v0.z, v0.w);
            __half2 h2 = __floats2half2_rn(v1.x, v1.y), h3 = __floats2half2_rn(v1.z, v1.w);
            uint4 u;
            u.x = *(uint32_t*)&h0; u.y = *(uint32_t*)&h1;
            u.z = *(uint32_t*)&h2; u.w = *(uint32_t*)&h3;
            dst[i] = u;
        }
    }
}

// fp32 weights -> fp16 (row-major, coalesced)
__global__ void k_cvt(const float4* __restrict__ W, uint4* __restrict__ O){
    size_t i = (size_t)blockIdx.x * blockDim.x + threadIdx.x;
    float4 v0 = W[2*i], v1 = W[2*i+1];
    __half2 h0 = __floats2half2_rn(v0.x, v0.y), h1 = __floats2half2_rn(v0.z, v0.w);
    __half2 h2 = __floats2half2_rn(v1.x, v1.y), h3 = __floats2half2_rn(v1.z, v1.w);
    uint4 u;
    u.x = *(uint32_t*)&h0; u.y = *(uint32_t*)&h1;
    u.z = *(uint32_t*)&h2; u.w = *(uint32_t*)&h3;
    O[i] = u;
}

// ---------------- HFMA2 SIMT GEMM: C(128x128) = A(128x2048) * W(128x2048)^T ----------------
// A row-major fp16, W row-major fp16. Chunked accumulation: fp16 chains of 8 k-steps,
// spilled to fp32. Accumulator pair (cols 2j,2j+1) = SwiGLU (glu,lin) pair.
template<bool SWIGLU>
__global__ __launch_bounds__(256, 2) void k_hgemm(const __half* __restrict__ Wh,
                                                  const float* __restrict__ Bb){
    int tile = blockIdx.x;
    if (tile >= g_ntiles) return;
    const int Nr = SWIGLU ? I2 : H;
    int e     = g_tile_e[tile];
    int sbase = tile * 128;
    int n0    = blockIdx.y * 128;
    const __half* A = (SWIGLU ? g_xh : g_yh) + (size_t)sbase * H;
    const __half* W = Wh + ((size_t)e * Nr + n0) * H;
    const float* bs = Bb + (size_t)e * Nr + n0;

    __shared__ __align__(16) __half2 Asd[16][128];  // [kk][row] duplicated pairs
    __shared__ __align__(16) __half  Bsh[16][128];  // [kk][ncol]

    int tid = threadIdx.x;
    int tm = (tid >> 4) << 3, tn = (tid & 15) << 3;
    int prow = tid >> 1, pkg = tid & 1;             // producer: row / k-group of 8
    const __half* Ap = A + (size_t)prow * H + pkg * 8;
    const __half* Bp = W + (size_t)prow * H + pkg * 8;

    __half2 hacc[8][4];
    float2  facc[8][4];
#pragma unroll
    for (int i = 0; i < 8; i++)
#pragma unroll
        for (int j = 0; j < 4; j++) facc[i][j] = make_float2(0.f, 0.f);

    uint4 pa = *(const uint4*)Ap;
    uint4 pb = *(const uint4*)Bp;

    for (int kt = 0; kt < 128; kt++){
        // producer: A duplicated half2 pairs, B raw halves (scatter into [kk][..])
        {
            uint32_t q[4] = { pa.x, pa.y, pa.z, pa.w };
#pragma unroll
            for (int qq = 0; qq < 4; qq++){
                uint32_t d0 = __byte_perm(q[qq], q[qq], 0x1010);  // (h_lo, h_lo)
                uint32_t d1 = __byte_perm(q[qq], q[qq], 0x3232);  // (h_hi, h_hi)
                Asd[pkg*8 + 2*qq    ][prow] = *(__half2*)&d0;
                Asd[pkg*8 + 2*qq + 1][prow] = *(__half2*)&d1;
            }
            union { uint4 u; __half h[8]; } bu; bu.u = pb;
#pragma unroll
            for (int j = 0; j < 8; j++) Bsh[pkg*8 + j][prow] = bu.h[j];
        }
        __syncthreads();
        if (kt + 1 < 128){
            pa = *(const uint4*)(Ap + (kt + 1) * 16);
            pb = *(const uint4*)(Bp + (kt + 1) * 16);
        }
#pragma unroll
        for (int kk = 0; kk < 16; kk++){
            __half2 a2[8], b2[4];
            *(uint4*)(a2)     = *(const uint4*)&Asd[kk][tm];
            *(uint4*)(a2 + 4) = *(const uint4*)&Asd[kk][tm + 4];
            *(uint4*)(b2)     = *(const uint4*)&Bsh[kk][tn];
            if ((kk & 7) == 0){
#pragma unroll
                for (int i = 0; i < 8; i++)
#pragma unroll
                    for (int j = 0; j < 4; j++) hacc[i][j] = __hmul2(a2[i], b2[j]);
            } else {
#pragma unroll
                for (int i = 0; i < 8; i++)
#pragma unroll
                    for (int j = 0; j < 4; j++) hacc[i][j] = __hfma2(a2[i], b2[j], hacc[i][j]);
            }
            if ((kk & 7) == 7){
#pragma unroll
                for (int i = 0; i < 8; i++)
#pragma unroll
                    for (int j = 0; j < 4; j++){
                        float2 f = __half22float2(hacc[i][j]);
                        facc[i][j].x += f.x; facc[i][j].y += f.y;
                    }
            }
        }
        __syncthreads();
    }

    if (SWIGLU){
#pragma unroll
        for (int i = 0; i < 8; i++){
            int slot = sbase + tm + i;
            __half* yr = g_yh + (size_t)slot * ID + ((n0 + tn) >> 1);
#pragma unroll
            for (int j = 0; j < 4; j++){
                float glu = facc[i][j].x + bs[tn + 2*j];
                float lin = facc[i][j].y + bs[tn + 2*j + 1];
                float s = 1.f / (1.f + expf(-1.702f * glu));
                yr[j] = __float2half_rn(glu * s * (lin + 1.f));
            }
        }
    } else {
#pragma unroll
        for (int i = 0; i < 8; i++){
            int slot = sbase + tm + i;
            float* orow = g_ob + (size_t)slot * H + n0 + tn;
#pragma unroll
            for (int j = 0; j < 4; j++){
                orow[2*j]     = facc[i][j].x + bs[tn + 2*j];
                orow[2*j + 1] = facc[i][j].y + bs[tn + 2*j + 1];
            }
        }
    }
}

__global__ void k_comb(float* __restrict__ out){
    int gid = blockIdx.x * blockDim.x + threadIdx.x;
    if (gid >= NTOK * (H/4)) return;
    int t = gid / (H/4), c4 = gid % (H/4);
    int s0 = g_slot[2*t], s1 = g_slot[2*t + 1];
    float2 w = g_wv[t];
    float4 a = *((const float4*)(g_ob + (size_t)s0 * H) + c4);
    float4 b = *((const float4*)(g_ob + (size_t)s1 * H) + c4);
    float4 r;
    r.x = w.x*a.x + w.y*b.x; r.y = w.x*a.y + w.y*b.y;
    r.z = w.x*a.z + w.y*b.z; r.w = w.x*a.w + w.y*b.w;
    *((float4*)out + gid) = r;
}

// ---------------- launcher ----------------
extern "C" void kernel_launch(void* const* d_in, const int* in_sizes, int n_in,
                              void* d_out, int out_size){
    const float* x  = (const float*)d_in[0];
    const float* gw = (const float*)d_in[1];
    const float* gb = (const float*)d_in[2];
    const float* w1 = (const float*)d_in[3];
    const float* b1 = (const float*)d_in[4];
    const float* w2 = (const float*)d_in[5];
    const float* b2 = (const float*)d_in[6];
    float* out = (float*)d_out;

    k_init<<<1, 32>>>();
    k_gate<<<NTOK/8, 256>>>(x, gw, gb);
    k_scan<<<1, 32>>>();
    k_gather<<<dim3(NEXP, NTOK/8), 256>>>(x);
    k_cvt<<<32768, 256>>>((const float4*)w1, (uint4*)g_w1h);
    k_cvt<<<16384, 256>>>((const float4*)w2, (uint4*)g_w2h);
    k_hgemm<true ><<<dim3(MAXTILES, I2/128), 256>>>(g_w1h, b1);
    k_hgemm<false><<<dim3(MAXTILES, H /128), 256>>>(g_w2h, b2);
    k_comb<<<(NTOK*(H/4) + 255)/256, 256>>>(out);
}